// round 5
// baseline (speedup 1.0000x reference)
#include <cuda_runtime.h>
#include <cuda_bf16.h>
#include <cstdint>

// Problem constants (fixed shapes)
#define N_TOK 8192     // D*H*W
#define BATCH 2
#define CC 96
#define CV 288
#define KIN 320

// ---------------------------------------------------------------------------
// Device scratch
// ---------------------------------------------------------------------------
__device__ __align__(128) __nv_bfloat16 g_Wks[CC * KIN];
__device__ float         g_bks[CC];
__device__ __align__(128) __nv_bfloat16 g_Wv[CV * KIN];
__device__ float         g_bv[CV];
__device__ __align__(128) __nv_bfloat16 g_Wq[CC * CC];
__device__ __align__(128) __nv_bfloat16 g_W6c[CC * CV];
__device__ __align__(128) __nv_bfloat16 g_ksum[(size_t)BATCH * N_TOK * CC];  // [B, N, 96] (log2e-scaled)
__device__ __align__(128) __nv_bfloat16 g_q[(size_t)BATCH * N_TOK * CC];     // [B, N, 96]
__device__ __align__(128) __nv_bfloat16 g_v[(size_t)BATCH * CV * N_TOK];     // [B, 288, N]

// ---------------------------------------------------------------------------
// Helpers
// ---------------------------------------------------------------------------
__device__ __forceinline__ uint32_t ld32bf(const __nv_bfloat16* p) {
    return *reinterpret_cast<const uint32_t*>(p);
}

__device__ __forceinline__ void mma_bf16(float& d0, float& d1, float& d2, float& d3,
                                         uint32_t a0, uint32_t a1, uint32_t a2, uint32_t a3,
                                         uint32_t b0, uint32_t b1)
{
    asm volatile(
        "mma.sync.aligned.m16n8k16.row.col.f32.bf16.bf16.f32 "
        "{%0,%1,%2,%3}, {%4,%5,%6,%7}, {%8,%9}, {%0,%1,%2,%3};\n"
        : "+f"(d0), "+f"(d1), "+f"(d2), "+f"(d3)
        : "r"(a0), "r"(a1), "r"(a2), "r"(a3), "r"(b0), "r"(b1));
}

__device__ __forceinline__ void ldsm4(uint32_t addr, uint32_t& r0, uint32_t& r1,
                                      uint32_t& r2, uint32_t& r3)
{
    asm volatile("ldmatrix.sync.aligned.m8n8.x4.shared.b16 {%0,%1,%2,%3}, [%4];\n"
                 : "=r"(r0), "=r"(r1), "=r"(r2), "=r"(r3) : "r"(addr));
}

__device__ __forceinline__ void cp16(uint32_t smem_dst, const void* gsrc)
{
    asm volatile("cp.async.cg.shared.global [%0], [%1], 16;\n"
                 :: "r"(smem_dst), "l"(gsrc));
}
__device__ __forceinline__ void cp_commit() { asm volatile("cp.async.commit_group;\n"); }
__device__ __forceinline__ void cp_wait0()  { asm volatile("cp.async.wait_group 0;\n"); }

// ---------------------------------------------------------------------------
// Prep kernel: combined weights; log2e folded into ksum weights/bias
// ---------------------------------------------------------------------------
__global__ void prep_kernel(const float* __restrict__ W1, const float* __restrict__ b1,
                            const float* __restrict__ W2, const float* __restrict__ b2,
                            const float* __restrict__ W3, const float* __restrict__ b3,
                            const float* __restrict__ W4, const float* __restrict__ b4,
                            const float* __restrict__ W5, const float* __restrict__ W6)
{
    const float LOG2E = 1.44269504088896341f;
    const int O_WKS = 0;
    const int O_WV  = O_WKS + CC * KIN;
    const int O_BKS = O_WV + CV * KIN;
    const int O_BV  = O_BKS + CC;
    const int O_WQ  = O_BV + CV;
    const int O_W6  = O_WQ + CC * CC;
    const int TOT   = O_W6 + CC * CV;

    for (int t = blockIdx.x * blockDim.x + threadIdx.x; t < TOT;
         t += gridDim.x * blockDim.x) {
        if (t < O_WV) {
            int c = t / KIN, i = t % KIN;
            float acc = 0.f;
            if (i < 128) {
                #pragma unroll 1
                for (int r = 0; r < 3; r++) {
                    const float* w3 = W3 + (c + 96 * r) * 288;
                    for (int j = 0; j < 192; j++) acc += w3[j] * W1[j * 128 + i];
                }
            } else {
                int ih = i - 128;
                #pragma unroll 1
                for (int r = 0; r < 3; r++) {
                    const float* w3 = W3 + (c + 96 * r) * 288 + 192;
                    for (int j = 0; j < 96; j++) acc += w3[j] * W2[j * 192 + ih];
                }
            }
            g_Wks[t] = __float2bfloat16(acc * LOG2E);
        } else if (t < O_BKS) {
            int u = t - O_WV;
            int c = u / KIN, i = u % KIN;
            float acc = 0.f;
            if (i < 128) {
                const float* w4 = W4 + c * 288;
                for (int j = 0; j < 192; j++) acc += w4[j] * W1[j * 128 + i];
            } else {
                int ih = i - 128;
                const float* w4 = W4 + c * 288 + 192;
                for (int j = 0; j < 96; j++) acc += w4[j] * W2[j * 192 + ih];
            }
            g_Wv[u] = __float2bfloat16(acc);
        } else if (t < O_BV) {
            int c = t - O_BKS;
            float acc = 0.f;
            for (int r = 0; r < 3; r++) {
                int row = c + 96 * r;
                acc += b3[row];
                const float* w3 = W3 + row * 288;
                for (int j = 0; j < 192; j++) acc += w3[j] * b1[j];
                for (int j = 0; j < 96; j++)  acc += w3[192 + j] * b2[j];
            }
            g_bks[c] = acc * LOG2E;
        } else if (t < O_WQ) {
            int c = t - O_BV;
            float acc = b4[c];
            const float* w4 = W4 + c * 288;
            for (int j = 0; j < 192; j++) acc += w4[j] * b1[j];
            for (int j = 0; j < 96; j++)  acc += w4[192 + j] * b2[j];
            g_bv[c] = acc;
        } else if (t < O_W6) {
            int u = t - O_WQ;
            g_Wq[u] = __float2bfloat16(W5[u]);
        } else {
            int u = t - O_W6;
            g_W6c[u] = __float2bfloat16(W6[u]);
        }
    }
}

// ---------------------------------------------------------------------------
// Projection GEMM body (R3-proven), callable per blockIdx.z
// ---------------------------------------------------------------------------
template<int M, int K, bool TOKMAJOR>
__device__ __forceinline__ void proj_body(
    const float* __restrict__ s0, int k0,
    const float* __restrict__ s1, int k1,
    const float* __restrict__ s2,
    const __nv_bfloat16* __restrict__ W,
    const float* __restrict__ bias,
    __nv_bfloat16* __restrict__ out,
    __nv_bfloat16* sX)
{
    const int tid = threadIdx.x;
    const int warp = tid >> 5;
    const int lane = tid & 31;
    const int t4 = lane >> 2;
    const int tm4 = lane & 3;
    const int b = blockIdx.y;
    const int n0 = blockIdx.x * 64;
    const int rw = warp * 16;

    const float* p0 = s0 + (size_t)b * k0 * N_TOK;
    const float* p1 = s1 + (size_t)b * k1 * N_TOK;
    const float* p2 = s2 + (size_t)b * (K - k0 - k1) * N_TOK;

    constexpr int MT = M / 8;
    float acc[MT][4];
    #pragma unroll
    for (int i = 0; i < MT; i++) { acc[i][0]=0.f; acc[i][1]=0.f; acc[i][2]=0.f; acc[i][3]=0.f; }

    for (int kc = 0; kc < K; kc += 32) {
        #pragma unroll
        for (int it = 0; it < 16; it++) {
            int idx = it * 128 + tid;
            int k = idx >> 6;
            int n = idx & 63;
            int r = kc + k;
            float v;
            if (r < k0)            v = p0[(size_t)r * N_TOK + n0 + n];
            else if (r < k0 + k1)  v = p1[(size_t)(r - k0) * N_TOK + n0 + n];
            else                   v = p2[(size_t)(r - k0 - k1) * N_TOK + n0 + n];
            sX[n * 40 + k] = __float2bfloat16(v);
        }
        __syncthreads();

        #pragma unroll
        for (int ks = 0; ks < 2; ks++) {
            const __nv_bfloat16* qb = sX + (rw + t4) * 40 + ks * 16 + 2 * tm4;
            uint32_t a0 = ld32bf(qb);
            uint32_t a1 = ld32bf(qb + 8 * 40);
            uint32_t a2 = ld32bf(qb + 8);
            uint32_t a3 = ld32bf(qb + 8 * 40 + 8);
            #pragma unroll
            for (int mt = 0; mt < MT; mt++) {
                const __nv_bfloat16* wb = W + (size_t)(mt * 8 + t4) * K + kc + ks * 16 + 2 * tm4;
                uint32_t b0 = ld32bf(wb);
                uint32_t b1 = ld32bf(wb + 8);
                mma_bf16(acc[mt][0], acc[mt][1], acc[mt][2], acc[mt][3],
                         a0, a1, a2, a3, b0, b1);
            }
        }
        __syncthreads();
    }

    int row0 = n0 + rw + t4;
    #pragma unroll
    for (int mt = 0; mt < MT; mt++) {
        int o = mt * 8 + 2 * tm4;
        float bz0 = bias[o], bz1 = bias[o + 1];
        float v0 = acc[mt][0] + bz0;
        float v1 = acc[mt][1] + bz1;
        float v2 = acc[mt][2] + bz0;
        float v3 = acc[mt][3] + bz1;
        if (TOKMAJOR) {
            *reinterpret_cast<__nv_bfloat162*>(out + ((size_t)(b * N_TOK + row0)) * M + o) =
                __floats2bfloat162_rn(v0, v1);
            *reinterpret_cast<__nv_bfloat162*>(out + ((size_t)(b * N_TOK + row0 + 8)) * M + o) =
                __floats2bfloat162_rn(v2, v3);
        } else {
            out[((size_t)(b * M + o)) * N_TOK + row0]         = __float2bfloat16(v0);
            out[((size_t)(b * M + o + 1)) * N_TOK + row0]     = __float2bfloat16(v1);
            out[((size_t)(b * M + o)) * N_TOK + row0 + 8]     = __float2bfloat16(v2);
            out[((size_t)(b * M + o + 1)) * N_TOK + row0 + 8] = __float2bfloat16(v3);
        }
    }
}

// Merged projection kernel: z=0 ksum, z=1 v, z=2 q. All CTAs resident together.
__global__ void __launch_bounds__(128) proj_all_kernel(
    const float* __restrict__ context, const float* __restrict__ h0,
    const float* __restrict__ h1, const float* __restrict__ x,
    const __nv_bfloat16* __restrict__ Wks, const float* __restrict__ bks,
    const __nv_bfloat16* __restrict__ Wv, const float* __restrict__ bv,
    const __nv_bfloat16* __restrict__ Wq, const float* __restrict__ b5,
    __nv_bfloat16* __restrict__ ksum_out, __nv_bfloat16* __restrict__ v_out,
    __nv_bfloat16* __restrict__ q_out)
{
    __shared__ __nv_bfloat16 sX[64 * 40];
    int z = blockIdx.z;
    if (z == 0) {
        proj_body<CC, KIN, true>(context, 128, h0, 96, h1, Wks, bks, ksum_out, sX);
    } else if (z == 1) {
        proj_body<CV, KIN, false>(context, 128, h0, 96, h1, Wv, bv, v_out, sX);
    } else {
        proj_body<CC, CC, true>(x, 96, x, 0, x, Wq, b5, q_out, sX);
    }
}

// ---------------------------------------------------------------------------
// Flash attention (HMMA) with smem-P PV restructure + fused W6 epilogue.
//   8 warps, Q tile 128, KV tiles 64, double-buffered cp.async.
//   Phase 1 (QK+exp): warp w computes S rows 16w..16w+15 (all 64 cols),
//       exp2, accumulates row sums, stores P (bf16) to sP[128][72].
//   Phase 2 (PV): warp w computes O rows 32*(w&3)..+32, cols 144*(w>>2)..+144.
//       V fragments per warp halved vs R3.
//   Epilogue: normalized O -> sE[128][296] bf16 -> W6 HMMA -> +b6 +x (fp32).
// smem map (bytes):
//   sm_l  f32[128]              @ 0
//   sP    bf16[128][72]         @ 1024    (18,432)
//   sQ    bf16[128][104]        @ 19,456  (26,624)
//   K bufs 2 x bf16[64][104]    @ 46,080  (2 x 13,312)
//   V bufs 2 x bf16[288][72]    @ 72,704  (2 x 41,472)  -> end 155,648
//   sE    bf16[128][296]        @ 46,080  (75,776; reuses K/V after loop)
// ---------------------------------------------------------------------------
#define KT 64
#define NIT (N_TOK / KT)
#define SML_OFF 0
#define SP_OFF  1024
#define SQ_OFF  19456
#define KB_OFF  46080
#define K_BUF   13312
#define VB_OFF  72704
#define V_BUF   41472
#define SE_OFF  KB_OFF
#define FLASH_SMEM_BYTES 155648

__global__ void __launch_bounds__(256, 1) flash_kernel(
    const __nv_bfloat16* __restrict__ qt,    // [B, N, 96]
    const __nv_bfloat16* __restrict__ kst,   // [B, N, 96] (log2e-scaled)
    const __nv_bfloat16* __restrict__ vv,    // [B, 288, N]
    const __nv_bfloat16* __restrict__ W6,    // [96, 288]
    const float* __restrict__ b6,
    const float* __restrict__ x,             // [B, 96, N]
    float* __restrict__ out)                 // [B, 96, N]
{
    extern __shared__ char smraw[];
    const int tid = threadIdx.x;
    const int wid = tid >> 5;
    const int lane = tid & 31;
    const int t4 = lane >> 2;
    const int tm4 = lane & 3;
    const int b = blockIdx.y;
    const int n0 = blockIdx.x * 128;
    const int rw = wid * 16;
    const int rq = wid & 3;      // PV row quarter
    const int colh = wid >> 2;   // PV col half

    const uint32_t smb = (uint32_t)__cvta_generic_to_shared(smraw);
    float* sm_l = reinterpret_cast<float*>(smraw + SML_OFF);
    __nv_bfloat16* sPp = reinterpret_cast<__nv_bfloat16*>(smraw + SP_OFF);
    __nv_bfloat16* sQp = reinterpret_cast<__nv_bfloat16*>(smraw + SQ_OFF);
    __nv_bfloat16* sEp = reinterpret_cast<__nv_bfloat16*>(smraw + SE_OFF);
    const uint32_t sP_b = smb + SP_OFF;
    const uint32_t sQ_b = smb + SQ_OFF;
    const uint32_t sK_b = smb + KB_OFF;
    const uint32_t sV_b = smb + VB_OFF;
    const uint32_t sE_b = smb + SE_OFF;

    // ldmatrix per-lane address components
    const int lg = lane >> 3;
    const int lr = lane & 7;
    const int rsel = (lg & 1) * 8 + lr;
    const int csel = (lg >> 1) * 8;
    const uint32_t aAddr0 = sQ_b + ((uint32_t)(rw + rsel) * 104 + csel) * 2;   // QK A
    const uint32_t kAddr0 = sK_b + ((uint32_t)rsel * 104 + csel) * 2;          // QK B
    const uint32_t pAddr0 = sP_b + ((uint32_t)(rq * 32 + rsel) * 72 + csel) * 2; // PV A
    const uint32_t vAddr0 = sV_b + ((uint32_t)rsel * 72 + csel) * 2
                          + (uint32_t)colh * (144 * 144);                       // PV B (col half)

    // ---- load Q tile ----
    {
        const __nv_bfloat16* qsrc = qt + ((size_t)(b * N_TOK + n0)) * 96;
        #pragma unroll
        for (int it = 0; it < 6; it++) {
            int idx = it * 256 + tid;
            int row = idx / 12;
            int c8 = idx % 12;
            *reinterpret_cast<uint4*>(sQp + row * 104 + c8 * 8) =
                *reinterpret_cast<const uint4*>(qsrc + (size_t)row * 96 + c8 * 8);
        }
    }

    // ---- async KV tile loader (R3-proven layout) ----
    const __nv_bfloat16* kbase = kst + ((size_t)b * N_TOK) * 96;
    const __nv_bfloat16* vbase = vv + ((size_t)b * CV) * N_TOK;
    auto issue_tile = [&](int mt_i, int bufi) {
        const int m0 = mt_i * KT;
        const uint32_t kd = sK_b + (uint32_t)bufi * K_BUF;
        const uint32_t vd = sV_b + (uint32_t)bufi * V_BUF;
        #pragma unroll
        for (int it = 0; it < 3; it++) {
            int c = it * 256 + tid;
            int row = c / 12, col = c % 12;
            cp16(kd + ((uint32_t)row * 104 + col * 8) * 2,
                 kbase + (size_t)(m0 + row) * 96 + col * 8);
        }
        #pragma unroll
        for (int it = 0; it < 9; it++) {
            int c = it * 256 + tid;
            int row = c >> 3, col = c & 7;
            cp16(vd + ((uint32_t)row * 72 + col * 8) * 2,
                 vbase + (size_t)row * N_TOK + m0 + col * 8);
        }
        cp_commit();
    };

    float o_[2][18][4];
    #pragma unroll
    for (int m = 0; m < 2; m++)
        #pragma unroll
        for (int i = 0; i < 18; i++) { o_[m][i][0]=0.f; o_[m][i][1]=0.f; o_[m][i][2]=0.f; o_[m][i][3]=0.f; }
    float l0 = 0.f, l1 = 0.f;

    issue_tile(0, 0);

    int buf = 0;
    for (int it = 0; it < NIT; it++) {
        cp_wait0();
        __syncthreads();      // tiles ready; previous PV reads of sP/sV done
        if (it + 1 < NIT) issue_tile(it + 1, buf ^ 1);

        const uint32_t kB = kAddr0 + (uint32_t)buf * K_BUF;
        const uint32_t vB = vAddr0 + (uint32_t)buf * V_BUF;

        // ---- S = Q @ K^T (warp: 16 rows x 64 cols) ----
        float s[8][4];
        #pragma unroll
        for (int j = 0; j < 8; j++) { s[j][0]=0.f; s[j][1]=0.f; s[j][2]=0.f; s[j][3]=0.f; }
        #pragma unroll
        for (int kk = 0; kk < 6; kk++) {
            uint32_t a0, a1, a2, a3;
            ldsm4(aAddr0 + kk * 32, a0, a1, a2, a3);
            #pragma unroll
            for (int jj = 0; jj < 4; jj++) {
                uint32_t b00, b01, b10, b11;
                ldsm4(kB + jj * (16 * 208) + kk * 32, b00, b01, b10, b11);
                mma_bf16(s[2*jj][0], s[2*jj][1], s[2*jj][2], s[2*jj][3],
                         a0, a1, a2, a3, b00, b10);
                mma_bf16(s[2*jj+1][0], s[2*jj+1][1], s[2*jj+1][2], s[2*jj+1][3],
                         a0, a1, a2, a3, b01, b11);
            }
        }

        // ---- P = exp2(S) (log2e pre-folded), row sums, store to sP ----
        #pragma unroll
        for (int j = 0; j < 8; j++) {
            s[j][0] = exp2f(s[j][0]);
            s[j][1] = exp2f(s[j][1]);
            s[j][2] = exp2f(s[j][2]);
            s[j][3] = exp2f(s[j][3]);
            l0 += s[j][0] + s[j][1];
            l1 += s[j][2] + s[j][3];
        }
        {
            const int r0 = rw + t4;
            #pragma unroll
            for (int j = 0; j < 8; j++) {
                int c = j * 8 + 2 * tm4;
                *reinterpret_cast<__nv_bfloat162*>(sPp + r0 * 72 + c) =
                    __floats2bfloat162_rn(s[j][0], s[j][1]);
                *reinterpret_cast<__nv_bfloat162*>(sPp + (r0 + 8) * 72 + c) =
                    __floats2bfloat162_rn(s[j][2], s[j][3]);
            }
        }
        __syncthreads();      // all P written

        // ---- O += P @ V^T (warp: 32 rows x 144 cols) ----
        #pragma unroll
        for (int g = 0; g < 4; g++) {
            uint32_t pa0[4], pa1[4];
            ldsm4(pAddr0 + g * 32, pa0[0], pa0[1], pa0[2], pa0[3]);
            ldsm4(pAddr0 + 2304 + g * 32, pa1[0], pa1[1], pa1[2], pa1[3]);  // +16 rows
            #pragma unroll
            for (int cc = 0; cc < 9; cc++) {
                uint32_t r0, r1, r2, r3;
                ldsm4(vB + cc * (16 * 144) + g * 32, r0, r1, r2, r3);
                mma_bf16(o_[0][2*cc][0], o_[0][2*cc][1], o_[0][2*cc][2], o_[0][2*cc][3],
                         pa0[0], pa0[1], pa0[2], pa0[3], r0, r2);
                mma_bf16(o_[0][2*cc+1][0], o_[0][2*cc+1][1], o_[0][2*cc+1][2], o_[0][2*cc+1][3],
                         pa0[0], pa0[1], pa0[2], pa0[3], r1, r3);
                mma_bf16(o_[1][2*cc][0], o_[1][2*cc][1], o_[1][2*cc][2], o_[1][2*cc][3],
                         pa1[0], pa1[1], pa1[2], pa1[3], r0, r2);
                mma_bf16(o_[1][2*cc+1][0], o_[1][2*cc+1][1], o_[1][2*cc+1][2], o_[1][2*cc+1][3],
                         pa1[0], pa1[1], pa1[2], pa1[3], r1, r3);
            }
        }
        buf ^= 1;
    }

    // ---- row sums -> sm_l ----
    l0 += __shfl_xor_sync(0xffffffffu, l0, 1);
    l0 += __shfl_xor_sync(0xffffffffu, l0, 2);
    l1 += __shfl_xor_sync(0xffffffffu, l1, 1);
    l1 += __shfl_xor_sync(0xffffffffu, l1, 2);
    if (tm4 == 0) {
        sm_l[rw + t4] = l0;
        sm_l[rw + t4 + 8] = l1;
    }
    __syncthreads();          // sm_l ready; all PV reads of V bufs done (sE reuse safe)

    // ---- normalized O -> sE[128][296] bf16 ----
    #pragma unroll
    for (int m = 0; m < 2; m++) {
        const int R = rq * 32 + m * 16 + t4;
        const float inv0 = 1.f / sm_l[R];
        const float inv1 = 1.f / sm_l[R + 8];
        #pragma unroll
        for (int ct = 0; ct < 18; ct++) {
            int c = colh * 144 + ct * 8 + 2 * tm4;
            *reinterpret_cast<__nv_bfloat162*>(sEp + (size_t)R * 296 + c) =
                __floats2bfloat162_rn(o_[m][ct][0] * inv0, o_[m][ct][1] * inv0);
            *reinterpret_cast<__nv_bfloat162*>(sEp + (size_t)(R + 8) * 296 + c) =
                __floats2bfloat162_rn(o_[m][ct][2] * inv1, o_[m][ct][3] * inv1);
        }
    }
    __syncthreads();

    // ---- W6 HMMA epilogue: out = W6 @ res + b6 + x ----
    const uint32_t aE = sE_b + ((uint32_t)(rw + rsel) * 296 + csel) * 2;
    float acc[12][4];
    #pragma unroll
    for (int i = 0; i < 12; i++) { acc[i][0]=0.f; acc[i][1]=0.f; acc[i][2]=0.f; acc[i][3]=0.f; }

    #pragma unroll
    for (int ks = 0; ks < 18; ks++) {
        uint32_t a0, a1, a2, a3;
        ldsm4(aE + ks * 32, a0, a1, a2, a3);
        #pragma unroll
        for (int mt = 0; mt < 12; mt++) {
            const __nv_bfloat16* wb = W6 + (size_t)(mt * 8 + t4) * CV + ks * 16 + 2 * tm4;
            uint32_t b0 = ld32bf(wb);
            uint32_t b1 = ld32bf(wb + 8);
            mma_bf16(acc[mt][0], acc[mt][1], acc[mt][2], acc[mt][3],
                     a0, a1, a2, a3, b0, b1);
        }
    }

    int n = n0 + rw + t4;
    #pragma unroll
    for (int mt = 0; mt < 12; mt++) {
        int o = mt * 8 + 2 * tm4;
        size_t i00 = ((size_t)(b * CC + o)) * N_TOK + n;
        size_t i01 = i00 + N_TOK;
        out[i00]     = acc[mt][0] + b6[o]     + x[i00];
        out[i01]     = acc[mt][1] + b6[o + 1] + x[i01];
        out[i00 + 8] = acc[mt][2] + b6[o]     + x[i00 + 8];
        out[i01 + 8] = acc[mt][3] + b6[o + 1] + x[i01 + 8];
    }
}

// ---------------------------------------------------------------------------
// Launch
// ---------------------------------------------------------------------------
extern "C" void kernel_launch(void* const* d_in, const int* in_sizes, int n_in,
                              void* d_out, int out_size)
{
    const float* context = (const float*)d_in[0];
    const float* h0 = (const float*)d_in[1];
    const float* h1 = (const float*)d_in[2];
    const float* x  = (const float*)d_in[3];
    const float* W1 = (const float*)d_in[4];
    const float* b1 = (const float*)d_in[5];
    const float* W2 = (const float*)d_in[6];
    const float* b2 = (const float*)d_in[7];
    const float* W3 = (const float*)d_in[8];
    const float* b3 = (const float*)d_in[9];
    const float* W4 = (const float*)d_in[10];
    const float* b4 = (const float*)d_in[11];
    const float* W5 = (const float*)d_in[12];
    const float* b5 = (const float*)d_in[13];
    const float* W6 = (const float*)d_in[14];
    const float* b6 = (const float*)d_in[15];
    float* out = (float*)d_out;

    void *pWks, *pBks, *pWv, *pBv, *pWq, *pW6, *pKsum, *pQ, *pV;
    cudaGetSymbolAddress(&pWks, g_Wks);
    cudaGetSymbolAddress(&pBks, g_bks);
    cudaGetSymbolAddress(&pWv, g_Wv);
    cudaGetSymbolAddress(&pBv, g_bv);
    cudaGetSymbolAddress(&pWq, g_Wq);
    cudaGetSymbolAddress(&pW6, g_W6c);
    cudaGetSymbolAddress(&pKsum, g_ksum);
    cudaGetSymbolAddress(&pQ, g_q);
    cudaGetSymbolAddress(&pV, g_v);

    cudaFuncSetAttribute(flash_kernel, cudaFuncAttributeMaxDynamicSharedMemorySize,
                         FLASH_SMEM_BYTES);

    prep_kernel<<<640, 256>>>(W1, b1, W2, b2, W3, b3, W4, b4, W5, W6);

    dim3 pgrid(N_TOK / 64, BATCH, 3);
    proj_all_kernel<<<pgrid, 128>>>(
        context, h0, h1, x,
        (const __nv_bfloat16*)pWks, (const float*)pBks,
        (const __nv_bfloat16*)pWv, (const float*)pBv,
        (const __nv_bfloat16*)pWq, b5,
        (__nv_bfloat16*)pKsum, (__nv_bfloat16*)pV, (__nv_bfloat16*)pQ);

    dim3 fgrid(N_TOK / 128, BATCH);
    flash_kernel<<<fgrid, 256, FLASH_SMEM_BYTES>>>(
        (const __nv_bfloat16*)pQ, (const __nv_bfloat16*)pKsum,
        (const __nv_bfloat16*)pV, (const __nv_bfloat16*)pW6,
        b6, x, out);
}

// round 6
// speedup vs baseline: 1.0789x; 1.0789x over previous
#include <cuda_runtime.h>
#include <cuda_bf16.h>
#include <cuda_fp16.h>
#include <cstdint>

// Problem constants (fixed shapes)
#define N_TOK 8192     // D*H*W
#define BATCH 2
#define CC 96
#define CV 288
#define KIN 320

// ---------------------------------------------------------------------------
// Device scratch
// ---------------------------------------------------------------------------
__device__ __align__(128) __nv_bfloat16 g_Wks[CC * KIN];
__device__ float         g_bks[CC];
__device__ __align__(128) __nv_bfloat16 g_Wv[CV * KIN];
__device__ float         g_bv[CV];
__device__ __align__(128) __nv_bfloat16 g_Wq[CC * CC];
__device__ __align__(128) __nv_bfloat16 g_W6c[CC * CV];
__device__ __align__(128) __nv_bfloat16 g_ksum[(size_t)BATCH * N_TOK * CC];  // [B, N, 96] (log2e-scaled)
__device__ __align__(128) __nv_bfloat16 g_q[(size_t)BATCH * N_TOK * CC];     // [B, N, 96]
__device__ __align__(128) __half        g_v[(size_t)BATCH * CV * N_TOK];     // [B, 288, N] fp16

// ---------------------------------------------------------------------------
// Helpers
// ---------------------------------------------------------------------------
__device__ __forceinline__ uint32_t ld32bf(const __nv_bfloat16* p) {
    return *reinterpret_cast<const uint32_t*>(p);
}

__device__ __forceinline__ void mma_bf16(float& d0, float& d1, float& d2, float& d3,
                                         uint32_t a0, uint32_t a1, uint32_t a2, uint32_t a3,
                                         uint32_t b0, uint32_t b1)
{
    asm volatile(
        "mma.sync.aligned.m16n8k16.row.col.f32.bf16.bf16.f32 "
        "{%0,%1,%2,%3}, {%4,%5,%6,%7}, {%8,%9}, {%0,%1,%2,%3};\n"
        : "+f"(d0), "+f"(d1), "+f"(d2), "+f"(d3)
        : "r"(a0), "r"(a1), "r"(a2), "r"(a3), "r"(b0), "r"(b1));
}

__device__ __forceinline__ void mma_f16(float& d0, float& d1, float& d2, float& d3,
                                        uint32_t a0, uint32_t a1, uint32_t a2, uint32_t a3,
                                        uint32_t b0, uint32_t b1)
{
    asm volatile(
        "mma.sync.aligned.m16n8k16.row.col.f32.f16.f16.f32 "
        "{%0,%1,%2,%3}, {%4,%5,%6,%7}, {%8,%9}, {%0,%1,%2,%3};\n"
        : "+f"(d0), "+f"(d1), "+f"(d2), "+f"(d3)
        : "r"(a0), "r"(a1), "r"(a2), "r"(a3), "r"(b0), "r"(b1));
}

__device__ __forceinline__ void ldsm4(uint32_t addr, uint32_t& r0, uint32_t& r1,
                                      uint32_t& r2, uint32_t& r3)
{
    asm volatile("ldmatrix.sync.aligned.m8n8.x4.shared.b16 {%0,%1,%2,%3}, [%4];\n"
                 : "=r"(r0), "=r"(r1), "=r"(r2), "=r"(r3) : "r"(addr));
}

__device__ __forceinline__ void cp16(uint32_t smem_dst, const void* gsrc)
{
    asm volatile("cp.async.cg.shared.global [%0], [%1], 16;\n"
                 :: "r"(smem_dst), "l"(gsrc));
}
__device__ __forceinline__ void cp_commit() { asm volatile("cp.async.commit_group;\n"); }
__device__ __forceinline__ void cp_wait0()  { asm volatile("cp.async.wait_group 0;\n"); }

// exp2 on two packed fp16 values; inputs fp32 (log2 domain), output f16x2 bits
__device__ __forceinline__ uint32_t ex2_f16x2(float a, float b)
{
    __half2 h = __floats2half2_rn(a, b);
    uint32_t hin = *reinterpret_cast<uint32_t*>(&h);
    uint32_t r;
    asm("ex2.approx.f16x2 %0, %1;" : "=r"(r) : "r"(hin));
    return r;
}

// ---------------------------------------------------------------------------
// Prep kernel v2: 4 threads per output element (j-loop quartered), quad-shfl
// reduce. log2e folded into ksum weights/bias.
// ---------------------------------------------------------------------------
#define P_O_WKS 0
#define P_O_WV  (CC * KIN)                 // 30720
#define P_O_BKS (P_O_WV + CV * KIN)        // 122880
#define P_O_BV  (P_O_BKS + CC)             // 122976
#define P_O_WQ  (P_O_BV + CV)              // 123264
#define P_O_W6  (P_O_WQ + CC * CC)         // 132480
#define P_TOT   (P_O_W6 + CC * CV)         // 160128

__global__ void __launch_bounds__(256) prep_kernel(
    const float* __restrict__ W1, const float* __restrict__ b1,
    const float* __restrict__ W2, const float* __restrict__ b2,
    const float* __restrict__ W3, const float* __restrict__ b3,
    const float* __restrict__ W4, const float* __restrict__ b4,
    const float* __restrict__ W5, const float* __restrict__ W6)
{
    const float LOG2E = 1.44269504088896341f;
    int t = blockIdx.x * blockDim.x + threadIdx.x;
    int e = t >> 2;
    int q = t & 3;
    if (e >= P_TOT) return;
    const uint32_t qmask = 0xFu << (threadIdx.x & 28);

    float acc = 0.f;

    if (e < P_O_WV) {
        int c = e / KIN, i = e % KIN;
        if (i < 128) {
            #pragma unroll 1
            for (int r = 0; r < 3; r++) {
                const float* w3 = W3 + (c + 96 * r) * 288;
                #pragma unroll 4
                for (int j = 48 * q; j < 48 * q + 48; j++) acc += w3[j] * W1[j * 128 + i];
            }
        } else {
            int ih = i - 128;
            #pragma unroll 1
            for (int r = 0; r < 3; r++) {
                const float* w3 = W3 + (c + 96 * r) * 288 + 192;
                #pragma unroll 4
                for (int j = 24 * q; j < 24 * q + 24; j++) acc += w3[j] * W2[j * 192 + ih];
            }
        }
        acc += __shfl_xor_sync(qmask, acc, 1);
        acc += __shfl_xor_sync(qmask, acc, 2);
        if (q == 0) g_Wks[e] = __float2bfloat16(acc * LOG2E);
    } else if (e < P_O_BKS) {
        int u = e - P_O_WV;
        int c = u / KIN, i = u % KIN;
        if (i < 128) {
            const float* w4 = W4 + c * 288;
            #pragma unroll 4
            for (int j = 48 * q; j < 48 * q + 48; j++) acc += w4[j] * W1[j * 128 + i];
        } else {
            int ih = i - 128;
            const float* w4 = W4 + c * 288 + 192;
            #pragma unroll 4
            for (int j = 24 * q; j < 24 * q + 24; j++) acc += w4[j] * W2[j * 192 + ih];
        }
        acc += __shfl_xor_sync(qmask, acc, 1);
        acc += __shfl_xor_sync(qmask, acc, 2);
        if (q == 0) g_Wv[u] = __float2bfloat16(acc);
    } else if (e < P_O_BV) {
        int c = e - P_O_BKS;
        #pragma unroll 1
        for (int r = 0; r < 3; r++) {
            int row = c + 96 * r;
            if (q == 0) acc += b3[row];
            const float* w3 = W3 + row * 288;
            for (int j = 48 * q; j < 48 * q + 48; j++) acc += w3[j] * b1[j];
            for (int j = 24 * q; j < 24 * q + 24; j++) acc += w3[192 + j] * b2[j];
        }
        acc += __shfl_xor_sync(qmask, acc, 1);
        acc += __shfl_xor_sync(qmask, acc, 2);
        if (q == 0) g_bks[c] = acc * LOG2E;
    } else if (e < P_O_WQ) {
        int c = e - P_O_BV;
        if (q == 0) acc += b4[c];
        const float* w4 = W4 + c * 288;
        for (int j = 48 * q; j < 48 * q + 48; j++) acc += w4[j] * b1[j];
        for (int j = 24 * q; j < 24 * q + 24; j++) acc += w4[192 + j] * b2[j];
        acc += __shfl_xor_sync(qmask, acc, 1);
        acc += __shfl_xor_sync(qmask, acc, 2);
        if (q == 0) g_bv[c] = acc;
    } else if (e < P_O_W6) {
        if (q == 0) {
            int u = e - P_O_WQ;
            g_Wq[u] = __float2bfloat16(W5[u]);
        }
    } else {
        if (q == 0) {
            int u = e - P_O_W6;
            g_W6c[u] = __float2bfloat16(W6[u]);
        }
    }
}

// ---------------------------------------------------------------------------
// Projection GEMM body. HALFOUT selects fp16 output (V path).
// ---------------------------------------------------------------------------
template<int M, int K, bool TOKMAJOR, bool HALFOUT>
__device__ __forceinline__ void proj_body(
    const float* __restrict__ s0, int k0,
    const float* __restrict__ s1, int k1,
    const float* __restrict__ s2,
    const __nv_bfloat16* __restrict__ W,
    const float* __restrict__ bias,
    void* __restrict__ outv,
    __nv_bfloat16* sX)
{
    const int tid = threadIdx.x;
    const int warp = tid >> 5;
    const int lane = tid & 31;
    const int t4 = lane >> 2;
    const int tm4 = lane & 3;
    const int b = blockIdx.y;
    const int n0 = blockIdx.x * 64;
    const int rw = warp * 16;

    const float* p0 = s0 + (size_t)b * k0 * N_TOK;
    const float* p1 = s1 + (size_t)b * k1 * N_TOK;
    const float* p2 = s2 + (size_t)b * (K - k0 - k1) * N_TOK;

    constexpr int MT = M / 8;
    float acc[MT][4];
    #pragma unroll
    for (int i = 0; i < MT; i++) { acc[i][0]=0.f; acc[i][1]=0.f; acc[i][2]=0.f; acc[i][3]=0.f; }

    for (int kc = 0; kc < K; kc += 32) {
        #pragma unroll
        for (int it = 0; it < 16; it++) {
            int idx = it * 128 + tid;
            int k = idx >> 6;
            int n = idx & 63;
            int r = kc + k;
            float v;
            if (r < k0)            v = p0[(size_t)r * N_TOK + n0 + n];
            else if (r < k0 + k1)  v = p1[(size_t)(r - k0) * N_TOK + n0 + n];
            else                   v = p2[(size_t)(r - k0 - k1) * N_TOK + n0 + n];
            sX[n * 40 + k] = __float2bfloat16(v);
        }
        __syncthreads();

        #pragma unroll
        for (int ks = 0; ks < 2; ks++) {
            const __nv_bfloat16* qb = sX + (rw + t4) * 40 + ks * 16 + 2 * tm4;
            uint32_t a0 = ld32bf(qb);
            uint32_t a1 = ld32bf(qb + 8 * 40);
            uint32_t a2 = ld32bf(qb + 8);
            uint32_t a3 = ld32bf(qb + 8 * 40 + 8);
            #pragma unroll
            for (int mt = 0; mt < MT; mt++) {
                const __nv_bfloat16* wb = W + (size_t)(mt * 8 + t4) * K + kc + ks * 16 + 2 * tm4;
                uint32_t b0 = ld32bf(wb);
                uint32_t b1 = ld32bf(wb + 8);
                mma_bf16(acc[mt][0], acc[mt][1], acc[mt][2], acc[mt][3],
                         a0, a1, a2, a3, b0, b1);
            }
        }
        __syncthreads();
    }

    int row0 = n0 + rw + t4;
    #pragma unroll
    for (int mt = 0; mt < MT; mt++) {
        int o = mt * 8 + 2 * tm4;
        float bz0 = bias[o], bz1 = bias[o + 1];
        float v0 = acc[mt][0] + bz0;
        float v1 = acc[mt][1] + bz1;
        float v2 = acc[mt][2] + bz0;
        float v3 = acc[mt][3] + bz1;
        if (TOKMAJOR) {
            __nv_bfloat16* out = (__nv_bfloat16*)outv;
            *reinterpret_cast<__nv_bfloat162*>(out + ((size_t)(b * N_TOK + row0)) * M + o) =
                __floats2bfloat162_rn(v0, v1);
            *reinterpret_cast<__nv_bfloat162*>(out + ((size_t)(b * N_TOK + row0 + 8)) * M + o) =
                __floats2bfloat162_rn(v2, v3);
        } else if (HALFOUT) {
            __half* out = (__half*)outv;
            out[((size_t)(b * M + o)) * N_TOK + row0]         = __float2half(v0);
            out[((size_t)(b * M + o + 1)) * N_TOK + row0]     = __float2half(v1);
            out[((size_t)(b * M + o)) * N_TOK + row0 + 8]     = __float2half(v2);
            out[((size_t)(b * M + o + 1)) * N_TOK + row0 + 8] = __float2half(v3);
        } else {
            __nv_bfloat16* out = (__nv_bfloat16*)outv;
            out[((size_t)(b * M + o)) * N_TOK + row0]         = __float2bfloat16(v0);
            out[((size_t)(b * M + o + 1)) * N_TOK + row0]     = __float2bfloat16(v1);
            out[((size_t)(b * M + o)) * N_TOK + row0 + 8]     = __float2bfloat16(v2);
            out[((size_t)(b * M + o + 1)) * N_TOK + row0 + 8] = __float2bfloat16(v3);
        }
    }
}

// Merged projection kernel: z=0 ksum, z=1 v (fp16), z=2 q.
__global__ void __launch_bounds__(128) proj_all_kernel(
    const float* __restrict__ context, const float* __restrict__ h0,
    const float* __restrict__ h1, const float* __restrict__ x,
    const __nv_bfloat16* __restrict__ Wks, const float* __restrict__ bks,
    const __nv_bfloat16* __restrict__ Wv, const float* __restrict__ bv,
    const __nv_bfloat16* __restrict__ Wq, const float* __restrict__ b5,
    __nv_bfloat16* __restrict__ ksum_out, __half* __restrict__ v_out,
    __nv_bfloat16* __restrict__ q_out)
{
    __shared__ __nv_bfloat16 sX[64 * 40];
    int z = blockIdx.z;
    if (z == 0) {
        proj_body<CC, KIN, true, false>(context, 128, h0, 96, h1, Wks, bks, ksum_out, sX);
    } else if (z == 1) {
        proj_body<CV, KIN, false, true>(context, 128, h0, 96, h1, Wv, bv, v_out, sX);
    } else {
        proj_body<CC, CC, true, false>(x, 96, x, 0, x, Wq, b5, q_out, sX);
    }
}

// ---------------------------------------------------------------------------
// Flash attention (R3 structure: no mid-iter syncs, register epilogue) with
// fp16 P/V and ex2.approx.f16x2 softmax.
// smem: sQ[128][104] | sK[2][64][104] | sV[2][288][72]  = 136,192 B
// ---------------------------------------------------------------------------
#define QT 128
#define KT 64
#define SQ_ELEMS (128 * 104)
#define SK_ELEMS (64 * 104)
#define SV_ELEMS (288 * 72)
#define FLASH_SMEM_BYTES ((SQ_ELEMS + 2 * SK_ELEMS + 2 * SV_ELEMS) * 2)

__global__ void __launch_bounds__(256, 1) flash_kernel(
    const __nv_bfloat16* __restrict__ qt,    // [B, N, 96]
    const __nv_bfloat16* __restrict__ kst,   // [B, N, 96] (log2e-scaled)
    const __half* __restrict__ vv,           // [B, 288, N] fp16
    const __nv_bfloat16* __restrict__ W6,    // [96, 288]
    const float* __restrict__ b6,
    const float* __restrict__ x,             // [B, 96, N]
    float* __restrict__ out)                 // [B, 96, N]
{
    extern __shared__ __nv_bfloat16 smem[];
    __nv_bfloat16* sQ = smem;

    const int tid = threadIdx.x;
    const int warp = tid >> 5;
    const int lane = tid & 31;
    const int t4 = lane >> 2;
    const int tm4 = lane & 3;
    const int b = blockIdx.y;
    const int n0 = blockIdx.x * QT;
    const int rw = warp * 16;

    const uint32_t smem_b = (uint32_t)__cvta_generic_to_shared(smem);
    const uint32_t sQ_b = smem_b;
    const uint32_t sK_b = smem_b + SQ_ELEMS * 2;
    const uint32_t sV_b = smem_b + (SQ_ELEMS + 2 * SK_ELEMS) * 2;

    const int lg = lane >> 3;
    const int lr = lane & 7;
    const int rsel = (lg & 1) * 8 + lr;
    const int csel = (lg >> 1) * 8;
    const uint32_t aAddr0 = sQ_b + ((rw + rsel) * 104 + csel) * 2;
    const uint32_t kAddr0 = sK_b + (rsel * 104 + csel) * 2;
    const uint32_t vAddr0 = sV_b + (rsel * 72 + csel) * 2;

    // ---- load Q tile ----
    {
        const __nv_bfloat16* qsrc = qt + ((size_t)(b * N_TOK + n0)) * 96;
        #pragma unroll
        for (int it = 0; it < 6; it++) {
            int idx = it * 256 + tid;
            int row = idx / 12;
            int c8 = idx % 12;
            *reinterpret_cast<uint4*>(sQ + row * 104 + c8 * 8) =
                *reinterpret_cast<const uint4*>(qsrc + (size_t)row * 96 + c8 * 8);
        }
    }

    // ---- async tile loader ----
    const __nv_bfloat16* kbase = kst + ((size_t)b * N_TOK) * 96;
    const __half* vbase = vv + ((size_t)b * CV) * N_TOK;
    auto issue_tile = [&](int mt_i, int buf) {
        const int m0 = mt_i * KT;
        #pragma unroll
        for (int it = 0; it < 3; it++) {
            int c = it * 256 + tid;
            int row = c / 12, col = c % 12;
            cp16(sK_b + (buf * SK_ELEMS + row * 104 + col * 8) * 2,
                 kbase + (size_t)(m0 + row) * 96 + col * 8);
        }
        #pragma unroll
        for (int it = 0; it < 9; it++) {
            int c = it * 256 + tid;
            int row = c >> 3, col = c & 7;
            cp16(sV_b + (buf * SV_ELEMS + row * 72 + col * 8) * 2,
                 vbase + (size_t)row * N_TOK + m0 + col * 8);
        }
        cp_commit();
    };

    float o_[36][4];
    #pragma unroll
    for (int i = 0; i < 36; i++) { o_[i][0]=0.f; o_[i][1]=0.f; o_[i][2]=0.f; o_[i][3]=0.f; }
    float l0 = 0.f, l1 = 0.f;

    issue_tile(0, 0);

    int buf = 0;
    for (int mt_i = 0; mt_i < N_TOK / KT; mt_i++) {
        cp_wait0();
        __syncthreads();
        if (mt_i + 1 < N_TOK / KT) issue_tile(mt_i + 1, buf ^ 1);

        const uint32_t kB = kAddr0 + buf * (SK_ELEMS * 2);
        const uint32_t vB = vAddr0 + buf * (SV_ELEMS * 2);

        // ---- S = Q @ K^T (bf16) ----
        float s[8][4];
        #pragma unroll
        for (int j = 0; j < 8; j++) { s[j][0]=0.f; s[j][1]=0.f; s[j][2]=0.f; s[j][3]=0.f; }
        #pragma unroll
        for (int kk = 0; kk < 6; kk++) {
            uint32_t a0, a1, a2, a3;
            ldsm4(aAddr0 + kk * 32, a0, a1, a2, a3);
            #pragma unroll
            for (int jj = 0; jj < 4; jj++) {
                uint32_t b00, b01, b10, b11;
                ldsm4(kB + jj * (16 * 208) + kk * 32, b00, b01, b10, b11);
                mma_bf16(s[2*jj][0], s[2*jj][1], s[2*jj][2], s[2*jj][3],
                         a0, a1, a2, a3, b00, b10);
                mma_bf16(s[2*jj+1][0], s[2*jj+1][1], s[2*jj+1][2], s[2*jj+1][3],
                         a0, a1, a2, a3, b01, b11);
            }
        }

        // ---- P = exp2(S) via f16x2 MUFU; row sums fp32; P stays fp16 ----
        uint32_t pa[4][4];
        #pragma unroll
        for (int j = 0; j < 8; j++) {
            uint32_t e01 = ex2_f16x2(s[j][0], s[j][1]);
            uint32_t e23 = ex2_f16x2(s[j][2], s[j][3]);
            float2 f01 = __half22float2(*reinterpret_cast<__half2*>(&e01));
            float2 f23 = __half22float2(*reinterpret_cast<__half2*>(&e23));
            l0 += f01.x + f01.y;
            l1 += f23.x + f23.y;
            pa[j >> 1][(j & 1) * 2]     = e01;
            pa[j >> 1][(j & 1) * 2 + 1] = e23;
        }

        // ---- O += P @ V^T (fp16 inputs, fp32 accum) ----
        #pragma unroll
        for (int g = 0; g < 4; g++) {
            #pragma unroll
            for (int cc = 0; cc < 18; cc++) {
                uint32_t r0, r1, r2, r3;
                ldsm4(vB + cc * (16 * 144) + g * 32, r0, r1, r2, r3);
                mma_f16(o_[2*cc][0], o_[2*cc][1], o_[2*cc][2], o_[2*cc][3],
                        pa[g][0], pa[g][1], pa[g][2], pa[g][3], r0, r2);
                mma_f16(o_[2*cc+1][0], o_[2*cc+1][1], o_[2*cc+1][2], o_[2*cc+1][3],
                        pa[g][0], pa[g][1], pa[g][2], pa[g][3], r1, r3);
            }
        }
        buf ^= 1;
        __syncthreads();
    }

    // ---- finalize softmax normalization ----
    l0 += __shfl_xor_sync(0xffffffffu, l0, 1);
    l0 += __shfl_xor_sync(0xffffffffu, l0, 2);
    l1 += __shfl_xor_sync(0xffffffffu, l1, 1);
    l1 += __shfl_xor_sync(0xffffffffu, l1, 2);
    float inv0 = 1.f / l0;
    float inv1 = 1.f / l1;

    // ---- fused epilogue: out = W6 @ res + b6 + x (C-frag == A-frag layout) ----
    float acc[12][4];
    #pragma unroll
    for (int i = 0; i < 12; i++) { acc[i][0]=0.f; acc[i][1]=0.f; acc[i][2]=0.f; acc[i][3]=0.f; }

    #pragma unroll
    for (int ks = 0; ks < 18; ks++) {
        __nv_bfloat162 ta0 = __floats2bfloat162_rn(o_[2*ks][0]*inv0,   o_[2*ks][1]*inv0);
        __nv_bfloat162 ta1 = __floats2bfloat162_rn(o_[2*ks][2]*inv1,   o_[2*ks][3]*inv1);
        __nv_bfloat162 ta2 = __floats2bfloat162_rn(o_[2*ks+1][0]*inv0, o_[2*ks+1][1]*inv0);
        __nv_bfloat162 ta3 = __floats2bfloat162_rn(o_[2*ks+1][2]*inv1, o_[2*ks+1][3]*inv1);
        uint32_t a0 = *reinterpret_cast<uint32_t*>(&ta0);
        uint32_t a1 = *reinterpret_cast<uint32_t*>(&ta1);
        uint32_t a2 = *reinterpret_cast<uint32_t*>(&ta2);
        uint32_t a3 = *reinterpret_cast<uint32_t*>(&ta3);
        #pragma unroll
        for (int mt = 0; mt < 12; mt++) {
            const __nv_bfloat16* wb = W6 + (size_t)(mt * 8 + t4) * CV + ks * 16 + 2 * tm4;
            uint32_t b0 = ld32bf(wb);
            uint32_t b1 = ld32bf(wb + 8);
            mma_bf16(acc[mt][0], acc[mt][1], acc[mt][2], acc[mt][3],
                     a0, a1, a2, a3, b0, b1);
        }
    }

    int n = n0 + rw + t4;
    #pragma unroll
    for (int mt = 0; mt < 12; mt++) {
        int o = mt * 8 + 2 * tm4;
        size_t i00 = ((size_t)(b * CC + o)) * N_TOK + n;
        size_t i01 = i00 + N_TOK;
        out[i00]     = acc[mt][0] + b6[o]     + x[i00];
        out[i01]     = acc[mt][1] + b6[o + 1] + x[i01];
        out[i00 + 8] = acc[mt][2] + b6[o]     + x[i00 + 8];
        out[i01 + 8] = acc[mt][3] + b6[o + 1] + x[i01 + 8];
    }
}

// ---------------------------------------------------------------------------
// Launch
// ---------------------------------------------------------------------------
extern "C" void kernel_launch(void* const* d_in, const int* in_sizes, int n_in,
                              void* d_out, int out_size)
{
    const float* context = (const float*)d_in[0];
    const float* h0 = (const float*)d_in[1];
    const float* h1 = (const float*)d_in[2];
    const float* x  = (const float*)d_in[3];
    const float* W1 = (const float*)d_in[4];
    const float* b1 = (const float*)d_in[5];
    const float* W2 = (const float*)d_in[6];
    const float* b2 = (const float*)d_in[7];
    const float* W3 = (const float*)d_in[8];
    const float* b3 = (const float*)d_in[9];
    const float* W4 = (const float*)d_in[10];
    const float* b4 = (const float*)d_in[11];
    const float* W5 = (const float*)d_in[12];
    const float* b5 = (const float*)d_in[13];
    const float* W6 = (const float*)d_in[14];
    const float* b6 = (const float*)d_in[15];
    float* out = (float*)d_out;

    void *pWks, *pBks, *pWv, *pBv, *pWq, *pW6, *pKsum, *pQ, *pV;
    cudaGetSymbolAddress(&pWks, g_Wks);
    cudaGetSymbolAddress(&pBks, g_bks);
    cudaGetSymbolAddress(&pWv, g_Wv);
    cudaGetSymbolAddress(&pBv, g_bv);
    cudaGetSymbolAddress(&pWq, g_Wq);
    cudaGetSymbolAddress(&pW6, g_W6c);
    cudaGetSymbolAddress(&pKsum, g_ksum);
    cudaGetSymbolAddress(&pQ, g_q);
    cudaGetSymbolAddress(&pV, g_v);

    cudaFuncSetAttribute(flash_kernel, cudaFuncAttributeMaxDynamicSharedMemorySize,
                         FLASH_SMEM_BYTES);

    prep_kernel<<<(P_TOT * 4 + 255) / 256, 256>>>(W1, b1, W2, b2, W3, b3, W4, b4, W5, W6);

    dim3 pgrid(N_TOK / 64, BATCH, 3);
    proj_all_kernel<<<pgrid, 128>>>(
        context, h0, h1, x,
        (const __nv_bfloat16*)pWks, (const float*)pBks,
        (const __nv_bfloat16*)pWv, (const float*)pBv,
        (const __nv_bfloat16*)pWq, b5,
        (__nv_bfloat16*)pKsum, (__half*)pV, (__nv_bfloat16*)pQ);

    dim3 fgrid(N_TOK / QT, BATCH);
    flash_kernel<<<fgrid, 256, FLASH_SMEM_BYTES>>>(
        (const __nv_bfloat16*)pQ, (const __nv_bfloat16*)pKsum,
        (const __half*)pV, (const __nv_bfloat16*)pW6,
        b6, x, out);
}